// round 1
// baseline (speedup 1.0000x reference)
#include <cuda_runtime.h>
#include <cuda_bf16.h>

#define NPTS 1024
#define FD 40
#define EPSF 1e-7f
#define TI 16
#define TJ 16

// Per-point precomputed partial activations of layer-0 fc0/fc1.
// A* = f_i @ W[0:40]  (+bias folded),  B* = f_j @ W[40:80]
__device__ float g_A1[NPTS * 32];
__device__ float g_B1[NPTS * 32];
__device__ float g_A0[NPTS * 32];
__device__ float g_B0[NPTS * 32];

// One block per point. 128 threads = 4 groups of 32 outputs (A1,B1,A0,B0).
__global__ void precompute_kernel(const float* __restrict__ feat,
                                  const float* __restrict__ w0,
                                  const float* __restrict__ b0,
                                  const float* __restrict__ w1,
                                  const float* __restrict__ b1)
{
    __shared__ float sfeat[FD];
    int i = blockIdx.x;
    int tid = threadIdx.x;
    if (tid < FD) sfeat[tid] = feat[i * FD + tid];
    __syncthreads();
    int o = tid & 31;
    int grp = tid >> 5;              // 0:A1 1:B1 2:A0 3:B0
    const float* w = (grp < 2) ? w1 : w0;
    int rowoff = (grp & 1) ? FD : 0; // B-side reads rows 40..79
    float acc = 0.f;
    if (!(grp & 1)) acc = (grp < 2) ? b1[o] : b0[o];  // fold bias into A-side only
#pragma unroll
    for (int k = 0; k < FD; k++)
        acc = fmaf(sfeat[k], w[(rowoff + k) * 32 + o], acc);
    float* dst = (grp == 0) ? g_A1 : (grp == 1) ? g_B1 : (grp == 2) ? g_A0 : g_B0;
    dst[i * 32 + o] = acc;
}

__global__ __launch_bounds__(256)
void pair_kernel(const float* __restrict__ pc, const float* __restrict__ nrm,
                 const float* __restrict__ dist,
                 const float* __restrict__ w0full, const float* __restrict__ w1full,
                 const float* __restrict__ w02, const float* __restrict__ b02,
                 const float* __restrict__ w11, const float* __restrict__ b11,
                 const float* __restrict__ w12, const float* __restrict__ b12,
                 const float* __restrict__ w20, const float* __restrict__ b20,
                 const float* __restrict__ w21, const float* __restrict__ b21,
                 const float* __restrict__ w22, const float* __restrict__ b22,
                 const float* __restrict__ fw,  const float* __restrict__ fb,
                 float* __restrict__ out)
{
    // ---- shared weights (broadcast-read) ----
    __shared__ __align__(16) float s_wp1[4 * 32], s_wp0[4 * 32];
    __shared__ __align__(16) float s_w02[32 * 32], s_b02[32];
    __shared__ __align__(16) float s_w11[32 * 32], s_b11[32];
    __shared__ __align__(16) float s_w12[32 * 32], s_b12[32];
    __shared__ __align__(16) float s_w20[32 * 16], s_b20[16];
    __shared__ __align__(16) float s_w21[32 * 16], s_b21[16];
    __shared__ __align__(16) float s_w22[16 * 16], s_b22[16];
    __shared__ __align__(16) float s_fw[16 * 66], s_fb[66];
    // ---- per-tile point data ----
    __shared__ __align__(16) float sA1[TI * 32], sA0[TI * 32];
    __shared__ __align__(16) float sB1[TJ * 32], sB0[TJ * 32];
    __shared__ float s_pci[TI * 3], s_ni[TI * 3], s_pcj[TJ * 3], s_nj[TJ * 3];

    const int tid = threadIdx.x;
    const int i0 = blockIdx.y * TI;
    const int j0 = blockIdx.x * TJ;

    // cooperative staging
    for (int idx = tid; idx < 128; idx += 256) {
        s_wp1[idx] = w1full[80 * 32 + idx];
        s_wp0[idx] = w0full[80 * 32 + idx];
    }
    for (int idx = tid; idx < 1024; idx += 256) {
        s_w02[idx] = w02[idx];
        s_w11[idx] = w11[idx];
        s_w12[idx] = w12[idx];
    }
    for (int idx = tid; idx < 512; idx += 256) {
        s_w20[idx] = w20[idx];
        s_w21[idx] = w21[idx];
    }
    if (tid < 256) s_w22[tid] = w22[tid];
    if (tid < 32) {
        s_b02[tid] = b02[tid]; s_b11[tid] = b11[tid]; s_b12[tid] = b12[tid];
    }
    if (tid < 16) {
        s_b20[tid] = b20[tid]; s_b21[tid] = b21[tid]; s_b22[tid] = b22[tid];
    }
    for (int idx = tid; idx < 16 * 66; idx += 256) s_fw[idx] = fw[idx];
    if (tid < 66) s_fb[tid] = fb[tid];
    for (int idx = tid; idx < TI * 32; idx += 256) {
        sA1[idx] = g_A1[i0 * 32 + idx];
        sA0[idx] = g_A0[i0 * 32 + idx];
    }
    for (int idx = tid; idx < TJ * 32; idx += 256) {
        sB1[idx] = g_B1[j0 * 32 + idx];
        sB0[idx] = g_B0[j0 * 32 + idx];
    }
    if (tid < TI * 3) { s_pci[tid] = pc[i0 * 3 + tid]; s_ni[tid] = nrm[i0 * 3 + tid]; }
    if (tid < TJ * 3) { s_pcj[tid] = pc[j0 * 3 + tid]; s_nj[tid] = nrm[j0 * 3 + tid]; }
    __syncthreads();

    const int tx = tid & (TJ - 1);
    const int ty = tid / TJ;
    const int i = i0 + ty;
    const int j = j0 + tx;

    // ---- PPF features ----
    const float d = dist[i * NPTS + j];
    const float xx0 = s_pci[ty * 3 + 0] - s_pcj[tx * 3 + 0];
    const float xx1 = s_pci[ty * 3 + 1] - s_pcj[tx * 3 + 1];
    const float xx2 = s_pci[ty * 3 + 2] - s_pcj[tx * 3 + 2];
    const float nix = s_ni[ty * 3 + 0], niy = s_ni[ty * 3 + 1], niz = s_ni[ty * 3 + 2];
    const float njx = s_nj[tx * 3 + 0], njy = s_nj[tx * 3 + 1], njz = s_nj[tx * 3 + 2];
    const float inv = 1.0f / (d + EPSF);
    const float xn0 = xx0 * inv, xn1 = xx1 * inv, xn2 = xx2 * inv;
    const float ppf0 = nix * xn0 + niy * xn1 + niz * xn2;
    const float ppf1 = njx * xn0 + njy * xn1 + njz * xn2;
    const float ppf2 = nix * njx + niy * njy + niz * njz;
    const float ppf3 = d;

    // ---- layer 0: hidden + residual-path pre-activations ----
    float h[32], r[32];
#pragma unroll
    for (int o = 0; o < 32; o++) {
        float a = sA1[ty * 32 + o] + sB1[tx * 32 + o];
        a = fmaf(ppf0, s_wp1[o], a);
        a = fmaf(ppf1, s_wp1[32 + o], a);
        a = fmaf(ppf2, s_wp1[64 + o], a);
        a = fmaf(ppf3, s_wp1[96 + o], a);
        h[o] = fmaxf(a, 0.f);
        float b = sA0[ty * 32 + o] + sB0[tx * 32 + o];
        b = fmaf(ppf0, s_wp0[o], b);
        b = fmaf(ppf1, s_wp0[32 + o], b);
        b = fmaf(ppf2, s_wp0[64 + o], b);
        b = fmaf(ppf3, s_wp0[96 + o], b);
        r[o] = b;
    }

    // x = h @ w02 + b02 + r   (vectorized weight rows: 1 LDS.128 per 4 FFMA)
    float x[32];
#pragma unroll
    for (int o = 0; o < 32; o++) x[o] = s_b02[o] + r[o];
#pragma unroll
    for (int k = 0; k < 32; k++) {
        const float hk = h[k];
#pragma unroll
        for (int o = 0; o < 32; o += 4) {
            float4 w = *(const float4*)(s_w02 + k * 32 + o);
            x[o + 0] = fmaf(hk, w.x, x[o + 0]);
            x[o + 1] = fmaf(hk, w.y, x[o + 1]);
            x[o + 2] = fmaf(hk, w.z, x[o + 2]);
            x[o + 3] = fmaf(hk, w.w, x[o + 3]);
        }
    }

    // ---- layer 1 (identity residual) ----
#pragma unroll
    for (int o = 0; o < 32; o++) h[o] = s_b11[o];
#pragma unroll
    for (int k = 0; k < 32; k++) {
        const float xk = x[k];
#pragma unroll
        for (int o = 0; o < 32; o += 4) {
            float4 w = *(const float4*)(s_w11 + k * 32 + o);
            h[o + 0] = fmaf(xk, w.x, h[o + 0]);
            h[o + 1] = fmaf(xk, w.y, h[o + 1]);
            h[o + 2] = fmaf(xk, w.z, h[o + 2]);
            h[o + 3] = fmaf(xk, w.w, h[o + 3]);
        }
    }
#pragma unroll
    for (int o = 0; o < 32; o++) h[o] = fmaxf(h[o], 0.f);
#pragma unroll
    for (int o = 0; o < 32; o++) x[o] += s_b12[o];
#pragma unroll
    for (int k = 0; k < 32; k++) {
        const float hk = h[k];
#pragma unroll
        for (int o = 0; o < 32; o += 4) {
            float4 w = *(const float4*)(s_w12 + k * 32 + o);
            x[o + 0] = fmaf(hk, w.x, x[o + 0]);
            x[o + 1] = fmaf(hk, w.y, x[o + 1]);
            x[o + 2] = fmaf(hk, w.z, x[o + 2]);
            x[o + 3] = fmaf(hk, w.w, x[o + 3]);
        }
    }

    // ---- layer 2 (32 -> 16, projected residual) ----
    float rr[16], hh[16];
#pragma unroll
    for (int o = 0; o < 16; o++) { rr[o] = s_b20[o]; hh[o] = s_b21[o]; }
#pragma unroll
    for (int k = 0; k < 32; k++) {
        const float xk = x[k];
#pragma unroll
        for (int o = 0; o < 16; o += 4) {
            float4 wa = *(const float4*)(s_w20 + k * 16 + o);
            float4 wb = *(const float4*)(s_w21 + k * 16 + o);
            rr[o + 0] = fmaf(xk, wa.x, rr[o + 0]);
            rr[o + 1] = fmaf(xk, wa.y, rr[o + 1]);
            rr[o + 2] = fmaf(xk, wa.z, rr[o + 2]);
            rr[o + 3] = fmaf(xk, wa.w, rr[o + 3]);
            hh[o + 0] = fmaf(xk, wb.x, hh[o + 0]);
            hh[o + 1] = fmaf(xk, wb.y, hh[o + 1]);
            hh[o + 2] = fmaf(xk, wb.z, hh[o + 2]);
            hh[o + 3] = fmaf(xk, wb.w, hh[o + 3]);
        }
    }
#pragma unroll
    for (int o = 0; o < 16; o++) hh[o] = fmaxf(hh[o], 0.f);
    float y[16];
#pragma unroll
    for (int o = 0; o < 16; o++) y[o] = s_b22[o] + rr[o];
#pragma unroll
    for (int k = 0; k < 16; k++) {
        const float hk = hh[k];
#pragma unroll
        for (int o = 0; o < 16; o += 4) {
            float4 w = *(const float4*)(s_w22 + k * 16 + o);
            y[o + 0] = fmaf(hk, w.x, y[o + 0]);
            y[o + 1] = fmaf(hk, w.y, y[o + 1]);
            y[o + 2] = fmaf(hk, w.z, y[o + 2]);
            y[o + 3] = fmaf(hk, w.w, y[o + 3]);
        }
    }

    // ---- final 16 -> 66 ----
    float oacc[66];
#pragma unroll
    for (int c = 0; c < 66; c++) oacc[c] = s_fb[c];
#pragma unroll
    for (int k = 0; k < 16; k++) {
        const float yk = y[k];
#pragma unroll
        for (int c = 0; c < 66; c += 2) {
            float2 w = *(const float2*)(s_fw + k * 66 + c);
            oacc[c + 0] = fmaf(yk, w.x, oacc[c + 0]);
            oacc[c + 1] = fmaf(yk, w.y, oacc[c + 1]);
        }
    }
    float* outp = out + (size_t)(i * NPTS + j) * 66;
#pragma unroll
    for (int c = 0; c < 66; c += 2)
        *(float2*)(outp + c) = make_float2(oacc[c], oacc[c + 1]);
}

extern "C" void kernel_launch(void* const* d_in, const int* in_sizes, int n_in,
                              void* d_out, int out_size)
{
    const float* pc   = (const float*)d_in[0];
    const float* nrm  = (const float*)d_in[1];
    const float* dist = (const float*)d_in[2];
    const float* feat = (const float*)d_in[3];
    const float* w0   = (const float*)d_in[4];
    const float* b0   = (const float*)d_in[5];
    const float* w1   = (const float*)d_in[6];
    const float* b1   = (const float*)d_in[7];
    const float* w02  = (const float*)d_in[8];
    const float* b02  = (const float*)d_in[9];
    const float* w11  = (const float*)d_in[10];
    const float* b11  = (const float*)d_in[11];
    const float* w12  = (const float*)d_in[12];
    const float* b12  = (const float*)d_in[13];
    const float* w20  = (const float*)d_in[14];
    const float* b20  = (const float*)d_in[15];
    const float* w21  = (const float*)d_in[16];
    const float* b21  = (const float*)d_in[17];
    const float* w22  = (const float*)d_in[18];
    const float* b22  = (const float*)d_in[19];
    const float* fw   = (const float*)d_in[20];
    const float* fb   = (const float*)d_in[21];
    float* out = (float*)d_out;

    precompute_kernel<<<NPTS, 128>>>(feat, w0, b0, w1, b1);
    dim3 grid(NPTS / TJ, NPTS / TI);
    pair_kernel<<<grid, 256>>>(pc, nrm, dist, w0, w1,
                               w02, b02, w11, b11, w12, b12,
                               w20, b20, w21, b21, w22, b22,
                               fw, fb, out);
}

// round 6
// speedup vs baseline: 1.0526x; 1.0526x over previous
#include <cuda_runtime.h>
#include <cuda_bf16.h>

#define NPTS 1024
#define FD 40
#define EPSF 1e-7f
#define TI 16
#define TJ 16

typedef unsigned long long u64;

__device__ __forceinline__ u64 pk2(float lo, float hi) {
    u64 r; asm("mov.b64 %0, {%1,%2};" : "=l"(r) : "f"(lo), "f"(hi)); return r;
}
__device__ __forceinline__ void upk2(u64 v, float& lo, float& hi) {
    asm("mov.b64 {%0,%1}, %2;" : "=f"(lo), "=f"(hi) : "l"(v));
}
__device__ __forceinline__ u64 fma2_(u64 a, u64 b, u64 c) {
    u64 d; asm("fma.rn.f32x2 %0, %1, %2, %3;" : "=l"(d) : "l"(a), "l"(b), "l"(c)); return d;
}
__device__ __forceinline__ u64 add2_(u64 a, u64 b) {
    u64 d; asm("add.rn.f32x2 %0, %1, %2;" : "=l"(d) : "l"(a), "l"(b)); return d;
}

// Per-point precomputed partial activations of layer-0 fc0/fc1.
__device__ float g_A1[NPTS * 32];
__device__ float g_B1[NPTS * 32];
__device__ float g_A0[NPTS * 32];
__device__ float g_B0[NPTS * 32];

__global__ void precompute_kernel(const float* __restrict__ feat,
                                  const float* __restrict__ w0,
                                  const float* __restrict__ b0,
                                  const float* __restrict__ w1,
                                  const float* __restrict__ b1)
{
    __shared__ float sfeat[FD];
    int i = blockIdx.x;
    int tid = threadIdx.x;
    if (tid < FD) sfeat[tid] = feat[i * FD + tid];
    __syncthreads();
    int o = tid & 31;
    int grp = tid >> 5;              // 0:A1 1:B1 2:A0 3:B0
    const float* w = (grp < 2) ? w1 : w0;
    int rowoff = (grp & 1) ? FD : 0;
    float acc = 0.f;
    if (!(grp & 1)) acc = (grp < 2) ? b1[o] : b0[o];  // bias folded into A-side
#pragma unroll
    for (int k = 0; k < FD; k++)
        acc = fmaf(sfeat[k], w[(rowoff + k) * 32 + o], acc);
    float* dst = (grp == 0) ? g_A1 : (grp == 1) ? g_B1 : (grp == 2) ? g_A0 : g_B0;
    dst[i * 32 + o] = acc;
}

__global__ __launch_bounds__(256, 2)
void pair_kernel(const float* __restrict__ pc, const float* __restrict__ nrm,
                 const float* __restrict__ dist,
                 const float* __restrict__ w0full, const float* __restrict__ w1full,
                 const float* __restrict__ w02, const float* __restrict__ b02,
                 const float* __restrict__ w11, const float* __restrict__ b11,
                 const float* __restrict__ w12, const float* __restrict__ b12,
                 const float* __restrict__ w20, const float* __restrict__ b20,
                 const float* __restrict__ w21, const float* __restrict__ b21,
                 const float* __restrict__ w22, const float* __restrict__ b22,
                 const float* __restrict__ fw,  const float* __restrict__ fb,
                 float* __restrict__ out)
{
    // ---- shared weights ----
    __shared__ __align__(16) float s_wp1[4 * 32], s_wp0[4 * 32];
    __shared__ __align__(16) float s_w02[32 * 32], s_b02[32];
    __shared__ __align__(16) float s_w11[32 * 32], s_b11[32];
    __shared__ __align__(16) float s_w12[32 * 32], s_b12[32];
    __shared__ __align__(16) float s_w20[32 * 16], s_b20[16];
    __shared__ __align__(16) float s_w21[32 * 16], s_b21[16];
    __shared__ __align__(16) float s_w22[16 * 16], s_b22[16];
    __shared__ __align__(16) float s_fw[16 * 68], s_fb[68];   // fw padded 66->68 cols
    // ---- per-tile point data ----
    __shared__ __align__(16) float sA1[TI * 32], sA0[TI * 32];
    __shared__ __align__(16) float sB1[TJ * 32], sB0[TJ * 32];
    __shared__ float s_pci[TI * 3], s_ni[TI * 3], s_pcj[TJ * 3], s_nj[TJ * 3];

    const int tid = threadIdx.x;
    const int i0 = blockIdx.y * TI;
    const int j0 = blockIdx.x * TJ;

    for (int idx = tid; idx < 128; idx += 256) {
        s_wp1[idx] = w1full[80 * 32 + idx];
        s_wp0[idx] = w0full[80 * 32 + idx];
    }
    for (int idx = tid; idx < 1024; idx += 256) {
        s_w02[idx] = w02[idx];
        s_w11[idx] = w11[idx];
        s_w12[idx] = w12[idx];
    }
    for (int idx = tid; idx < 512; idx += 256) {
        s_w20[idx] = w20[idx];
        s_w21[idx] = w21[idx];
    }
    if (tid < 256) s_w22[tid] = w22[tid];
    if (tid < 32) { s_b02[tid] = b02[tid]; s_b11[tid] = b11[tid]; s_b12[tid] = b12[tid]; }
    if (tid < 16) { s_b20[tid] = b20[tid]; s_b21[tid] = b21[tid]; s_b22[tid] = b22[tid]; }
    for (int idx = tid; idx < 16 * 68; idx += 256) {
        int row = idx / 68, col = idx % 68;
        s_fw[idx] = (col < 66) ? fw[row * 66 + col] : 0.f;
    }
    if (tid < 68) s_fb[tid] = (tid < 66) ? fb[tid] : 0.f;
    for (int idx = tid; idx < TI * 32; idx += 256) {
        sA1[idx] = g_A1[i0 * 32 + idx];
        sA0[idx] = g_A0[i0 * 32 + idx];
    }
    for (int idx = tid; idx < TJ * 32; idx += 256) {
        sB1[idx] = g_B1[j0 * 32 + idx];
        sB0[idx] = g_B0[j0 * 32 + idx];
    }
    if (tid < TI * 3) { s_pci[tid] = pc[i0 * 3 + tid]; s_ni[tid] = nrm[i0 * 3 + tid]; }
    if (tid < TJ * 3) { s_pcj[tid] = pc[j0 * 3 + tid]; s_nj[tid] = nrm[j0 * 3 + tid]; }
    __syncthreads();

    const int tx = tid & (TJ - 1);
    const int ty = tid / TJ;
    const int i = i0 + ty;
    const int j = j0 + tx;

    // ---- PPF features ----
    const float d = dist[i * NPTS + j];
    const float xx0 = s_pci[ty * 3 + 0] - s_pcj[tx * 3 + 0];
    const float xx1 = s_pci[ty * 3 + 1] - s_pcj[tx * 3 + 1];
    const float xx2 = s_pci[ty * 3 + 2] - s_pcj[tx * 3 + 2];
    const float nix = s_ni[ty * 3 + 0], niy = s_ni[ty * 3 + 1], niz = s_ni[ty * 3 + 2];
    const float njx = s_nj[tx * 3 + 0], njy = s_nj[tx * 3 + 1], njz = s_nj[tx * 3 + 2];
    const float inv = 1.0f / (d + EPSF);
    const float xn0 = xx0 * inv, xn1 = xx1 * inv, xn2 = xx2 * inv;
    const u64 p0 = pk2(nix * xn0 + niy * xn1 + niz * xn2, nix * xn0 + niy * xn1 + niz * xn2);
    const u64 p1 = pk2(njx * xn0 + njy * xn1 + njz * xn2, njx * xn0 + njy * xn1 + njz * xn2);
    const u64 p2 = pk2(nix * njx + niy * njy + niz * njz, nix * njx + niy * njy + niz * njz);
    const u64 p3 = pk2(d, d);

    const u64* A1p = (const u64*)(sA1 + ty * 32);
    const u64* B1p = (const u64*)(sB1 + tx * 32);
    const u64* A0p = (const u64*)(sA0 + ty * 32);
    const u64* B0p = (const u64*)(sB0 + tx * 32);
    const u64* wp1p = (const u64*)s_wp1;
    const u64* wp0p = (const u64*)s_wp0;
    const u64* b02p = (const u64*)s_b02;

    // ---- layer 0: hidden (relu) + residual path straight into packed accumulators ----
    u64 xp[16];
    float h[32];
#pragma unroll
    for (int o2 = 0; o2 < 16; o2++) {
        u64 a = add2_(A1p[o2], B1p[o2]);
        a = fma2_(p0, wp1p[o2], a);
        a = fma2_(p1, wp1p[16 + o2], a);
        a = fma2_(p2, wp1p[32 + o2], a);
        a = fma2_(p3, wp1p[48 + o2], a);
        float lo, hi; upk2(a, lo, hi);
        h[2 * o2] = fmaxf(lo, 0.f);
        h[2 * o2 + 1] = fmaxf(hi, 0.f);
        u64 b = add2_(A0p[o2], B0p[o2]);
        b = fma2_(p0, wp0p[o2], b);
        b = fma2_(p1, wp0p[16 + o2], b);
        b = fma2_(p2, wp0p[32 + o2], b);
        b = fma2_(p3, wp0p[48 + o2], b);
        xp[o2] = add2_(b, b02p[o2]);
    }

    // x += h @ w02  (packed: 2 cols per fma)
    {
        const u64* wp = (const u64*)s_w02;
#pragma unroll
        for (int k = 0; k < 32; k++) {
            const u64 hb = pk2(h[k], h[k]);
#pragma unroll
            for (int o2 = 0; o2 < 16; o2 += 2) {
                ulonglong2 w = *(const ulonglong2*)(wp + k * 16 + o2);
                xp[o2 + 0] = fma2_(hb, w.x, xp[o2 + 0]);
                xp[o2 + 1] = fma2_(hb, w.y, xp[o2 + 1]);
            }
        }
    }

    // ---- layer 1 (identity residual) ----
    {
        const u64* b11p = (const u64*)s_b11;
        const u64* b12p = (const u64*)s_b12;
        const u64* w1p = (const u64*)s_w11;
        const u64* w2p = (const u64*)s_w12;
        u64 hp[16];
#pragma unroll
        for (int o2 = 0; o2 < 16; o2++) hp[o2] = b11p[o2];
#pragma unroll
        for (int k2 = 0; k2 < 16; k2++) {
            float x0, x1; upk2(xp[k2], x0, x1);
            const u64 hb0 = pk2(x0, x0);
            const u64 hb1 = pk2(x1, x1);
#pragma unroll
            for (int o2 = 0; o2 < 16; o2 += 2) {
                ulonglong2 wa = *(const ulonglong2*)(w1p + (2 * k2) * 16 + o2);
                ulonglong2 wb = *(const ulonglong2*)(w1p + (2 * k2 + 1) * 16 + o2);
                hp[o2 + 0] = fma2_(hb0, wa.x, hp[o2 + 0]);
                hp[o2 + 1] = fma2_(hb0, wa.y, hp[o2 + 1]);
                hp[o2 + 0] = fma2_(hb1, wb.x, hp[o2 + 0]);
                hp[o2 + 1] = fma2_(hb1, wb.y, hp[o2 + 1]);
            }
        }
#pragma unroll
        for (int o2 = 0; o2 < 16; o2++) {
            float lo, hi; upk2(hp[o2], lo, hi);
            h[2 * o2] = fmaxf(lo, 0.f);
            h[2 * o2 + 1] = fmaxf(hi, 0.f);
            xp[o2] = add2_(xp[o2], b12p[o2]);
        }
#pragma unroll
        for (int k = 0; k < 32; k++) {
            const u64 hb = pk2(h[k], h[k]);
#pragma unroll
            for (int o2 = 0; o2 < 16; o2 += 2) {
                ulonglong2 w = *(const ulonglong2*)(w2p + k * 16 + o2);
                xp[o2 + 0] = fma2_(hb, w.x, xp[o2 + 0]);
                xp[o2 + 1] = fma2_(hb, w.y, xp[o2 + 1]);
            }
        }
    }

    // ---- layer 2 (32 -> 16, projected residual) ----
    u64 yp[8];
    float hh[16];
    {
        const u64* b20p = (const u64*)s_b20;
        const u64* b21p = (const u64*)s_b21;
        const u64* b22p = (const u64*)s_b22;
        const u64* w20p = (const u64*)s_w20;
        const u64* w21p = (const u64*)s_w21;
        const u64* w22p = (const u64*)s_w22;
        u64 rrp[8], hhp[8];
#pragma unroll
        for (int o2 = 0; o2 < 8; o2++) { rrp[o2] = b20p[o2]; hhp[o2] = b21p[o2]; }
#pragma unroll
        for (int k2 = 0; k2 < 16; k2++) {
            float x0, x1; upk2(xp[k2], x0, x1);
            const u64 hb0 = pk2(x0, x0);
            const u64 hb1 = pk2(x1, x1);
#pragma unroll
            for (int o2 = 0; o2 < 8; o2 += 2) {
                ulonglong2 wa0 = *(const ulonglong2*)(w20p + (2 * k2) * 8 + o2);
                ulonglong2 wa1 = *(const ulonglong2*)(w20p + (2 * k2 + 1) * 8 + o2);
                ulonglong2 wb0 = *(const ulonglong2*)(w21p + (2 * k2) * 8 + o2);
                ulonglong2 wb1 = *(const ulonglong2*)(w21p + (2 * k2 + 1) * 8 + o2);
                rrp[o2 + 0] = fma2_(hb0, wa0.x, rrp[o2 + 0]);
                rrp[o2 + 1] = fma2_(hb0, wa0.y, rrp[o2 + 1]);
                rrp[o2 + 0] = fma2_(hb1, wa1.x, rrp[o2 + 0]);
                rrp[o2 + 1] = fma2_(hb1, wa1.y, rrp[o2 + 1]);
                hhp[o2 + 0] = fma2_(hb0, wb0.x, hhp[o2 + 0]);
                hhp[o2 + 1] = fma2_(hb0, wb0.y, hhp[o2 + 1]);
                hhp[o2 + 0] = fma2_(hb1, wb1.x, hhp[o2 + 0]);
                hhp[o2 + 1] = fma2_(hb1, wb1.y, hhp[o2 + 1]);
            }
        }
#pragma unroll
        for (int o2 = 0; o2 < 8; o2++) {
            float lo, hi; upk2(hhp[o2], lo, hi);
            hh[2 * o2] = fmaxf(lo, 0.f);
            hh[2 * o2 + 1] = fmaxf(hi, 0.f);
            yp[o2] = add2_(rrp[o2], b22p[o2]);
        }
#pragma unroll
        for (int k = 0; k < 16; k++) {
            const u64 hb = pk2(hh[k], hh[k]);
#pragma unroll
            for (int o2 = 0; o2 < 8; o2 += 2) {
                ulonglong2 w = *(const ulonglong2*)(w22p + k * 8 + o2);
                yp[o2 + 0] = fma2_(hb, w.x, yp[o2 + 0]);
                yp[o2 + 1] = fma2_(hb, w.y, yp[o2 + 1]);
            }
        }
    }

    // y scalars for final broadcasts
    float ys[16];
#pragma unroll
    for (int o2 = 0; o2 < 8; o2++) upk2(yp[o2], ys[2 * o2], ys[2 * o2 + 1]);

    // ---- final 16 -> 66 in 3 column chunks (24, 24, 18) -> no giant live accumulator ----
    float* outp = out + (size_t)(i * NPTS + j) * 66;
    const u64* fwp = (const u64*)s_fw;   // 34 pairs per row
    const u64* fbp = (const u64*)s_fb;
#pragma unroll
    for (int chunk = 0; chunk < 3; chunk++) {
        const int c0 = chunk * 24;                    // 0, 24, 48
        const int cn2 = (chunk == 2) ? 9 : 12;        // packed count
        u64 acc[12];
#pragma unroll
        for (int t = 0; t < 12; t++) if (t < cn2) acc[t] = fbp[c0 / 2 + t];
#pragma unroll
        for (int k = 0; k < 16; k++) {
            const u64 yb = pk2(ys[k], ys[k]);
            const u64* row = fwp + k * 34 + c0 / 2;
#pragma unroll
            for (int t = 0; t < 12; t += 2) {
                if (t + 1 < cn2) {
                    ulonglong2 w = *(const ulonglong2*)(row + t);
                    acc[t + 0] = fma2_(yb, w.x, acc[t + 0]);
                    acc[t + 1] = fma2_(yb, w.y, acc[t + 1]);
                } else if (t < cn2) {
                    acc[t] = fma2_(yb, row[t], acc[t]);
                }
            }
        }
#pragma unroll
        for (int t = 0; t < 12; t++)
            if (t < cn2) *(u64*)(outp + c0 + 2 * t) = acc[t];
    }
}

extern "C" void kernel_launch(void* const* d_in, const int* in_sizes, int n_in,
                              void* d_out, int out_size)
{
    const float* pc   = (const float*)d_in[0];
    const float* nrm  = (const float*)d_in[1];
    const float* dist = (const float*)d_in[2];
    const float* feat = (const float*)d_in[3];
    const float* w0   = (const float*)d_in[4];
    const float* b0   = (const float*)d_in[5];
    const float* w1   = (const float*)d_in[6];
    const float* b1   = (const float*)d_in[7];
    const float* w02  = (const float*)d_in[8];
    const float* b02  = (const float*)d_in[9];
    const float* w11  = (const float*)d_in[10];
    const float* b11  = (const float*)d_in[11];
    const float* w12  = (const float*)d_in[12];
    const float* b12  = (const float*)d_in[13];
    const float* w20  = (const float*)d_in[14];
    const float* b20  = (const float*)d_in[15];
    const float* w21  = (const float*)d_in[16];
    const float* b21  = (const float*)d_in[17];
    const float* w22  = (const float*)d_in[18];
    const float* b22  = (const float*)d_in[19];
    const float* fw   = (const float*)d_in[20];
    const float* fb   = (const float*)d_in[21];
    float* out = (float*)d_out;

    precompute_kernel<<<NPTS, 128>>>(feat, w0, b0, w1, b1);
    dim3 grid(NPTS / TJ, NPTS / TI);
    pair_kernel<<<grid, 256>>>(pc, nrm, dist, w0, w1,
                               w02, b02, w11, b11, w12, b12,
                               w20, b20, w21, b21, w22, b22,
                               fw, fb, out);
}